// round 15
// baseline (speedup 1.0000x reference)
#include <cuda_runtime.h>
#include <cuda_bf16.h>
#include <math.h>
#include <stdint.h>

// Problem constants
static constexpr int NN   = 100000;
static constexpr int NE   = 1600000;
static constexpr int FIN  = 500;
static constexpr int HID  = 64;
static constexpr int NCLS = 40;

static constexpr int TILE = 512;
static constexpr int NB   = (NN + TILE - 1) / TILE;    // 196

// ---------------- scratch ----------------------------------------------------
__device__ float g_dinv  [NN];
__device__ float g_h1s   [NN * HID];
__device__ float g_t1    [NN * HID];
__device__ float g_gs    [NN * NCLS];
__device__ int   g_esrc  [NE];
__device__ int   g_cnt   [NN];
__device__ int   g_pos   [NN];
__device__ int   g_rowptr[NN + 1];
__device__ int   g_bsum  [256];
__device__ int   g_boff  [256];
__device__ int   g_is64;
__device__ __align__(16) uint32_t g_w1h[64 * 256];
__device__ __align__(16) uint32_t g_w1l[64 * 256];

// ---------------- prep -------------------------------------------------------
__global__ void k_prep(const int* __restrict__ e, const float* __restrict__ W1) {
    int i = blockIdx.x * blockDim.x + threadIdx.x;
    if (i == 0) {
        int all0 = 1;
        #pragma unroll 1
        for (int j = 0; j < 64; j++) all0 &= (e[2 * j + 1] == 0);
        g_is64 = all0;
    }
    if (i < NN) { g_cnt[i] = 0; g_pos[i] = 0; }
    if (i < 64 * 256) {
        int n = i >> 8, kp = i & 255;
        int k0 = 2 * kp, k1 = 2 * kp + 1;
        float f0 = (k0 < FIN) ? W1[k0 * HID + n] : 0.f;
        float f1 = (k1 < FIN) ? W1[k1 * HID + n] : 0.f;
        uint32_t u0 = __float_as_uint(f0), u1 = __float_as_uint(f1);
        uint32_t hi = __byte_perm(u0, u1, 0x7632);
        float l0 = f0 - __uint_as_float(u0 & 0xFFFF0000u);
        float l1 = f1 - __uint_as_float(u1 & 0xFFFF0000u);
        uint32_t lo;
        asm("cvt.rn.bf16x2.f32 %0, %1, %2;" : "=r"(lo) : "f"(l1), "f"(l0));
        g_w1h[i] = hi;
        g_w1l[i] = lo;
    }
}

__global__ void k_hist(const int* __restrict__ e) {
    int i = blockIdx.x * blockDim.x + threadIdx.x;
    if (i >= NE) return;
    int d = g_is64 ? e[2 * (NE + i)] : e[NE + i];
    atomicAdd(&g_cnt[d], 1);
}

__global__ __launch_bounds__(256) void k_tilesum() {
    __shared__ int sred[256];
    int t = threadIdx.x;
    int base = blockIdx.x * TILE + t * 2;
    int c0 = (base     < NN) ? g_cnt[base]     : 0;
    int c1 = (base + 1 < NN) ? g_cnt[base + 1] : 0;
    sred[t] = c0 + c1;
    __syncthreads();
    #pragma unroll
    for (int o = 128; o; o >>= 1) {
        if (t < o) sred[t] += sred[t + o];
        __syncthreads();
    }
    if (t == 0) g_bsum[blockIdx.x] = sred[0];
}

// ---------------- GEMM1 (mma.sync split-bf16, bulk-copy 3-stage) -------------
__device__ __forceinline__ void mma16816(float* c,
                                         uint32_t a0, uint32_t a1, uint32_t a2, uint32_t a3,
                                         uint32_t b0, uint32_t b1) {
    asm volatile(
        "mma.sync.aligned.m16n8k16.row.col.f32.bf16.bf16.f32 "
        "{%0,%1,%2,%3}, {%4,%5,%6,%7}, {%8,%9}, {%0,%1,%2,%3};"
        : "+f"(c[0]), "+f"(c[1]), "+f"(c[2]), "+f"(c[3])
        : "r"(a0), "r"(a1), "r"(a2), "r"(a3), "r"(b0), "r"(b1));
}
__device__ __forceinline__ void ldsm4(uint32_t* r, uint32_t addr) {
    asm volatile("ldmatrix.sync.aligned.m8n8.x4.shared.b16 {%0,%1,%2,%3}, [%4];"
                 : "=r"(r[0]), "=r"(r[1]), "=r"(r[2]), "=r"(r[3]) : "r"(addr));
}
__device__ __forceinline__ uint32_t smem_u32(const void* p) {
    uint32_t a;
    asm("{ .reg .u64 t; cvta.to.shared.u64 t, %1; cvt.u32.u64 %0, t; }" : "=r"(a) : "l"(p));
    return a;
}
__device__ __forceinline__ void cvt2(float2 p, uint32_t& hi, uint32_t& lo) {
    uint32_t u0 = __float_as_uint(p.x), u1 = __float_as_uint(p.y);
    hi = __byte_perm(u0, u1, 0x7632);
    float l0 = p.x - __uint_as_float(u0 & 0xFFFF0000u);
    float l1 = p.y - __uint_as_float(u1 & 0xFFFF0000u);
    asm("cvt.rn.bf16x2.f32 %0, %1, %2;" : "=r"(lo) : "f"(l1), "f"(l0));
}
__device__ __forceinline__ void bulk_cp(uint32_t dst, const void* src, uint32_t bytes,
                                        uint32_t mbar) {
    asm volatile(
        "cp.async.bulk.shared::cluster.global.mbarrier::complete_tx::bytes "
        "[%0], [%1], %2, [%3];"
        :: "r"(dst), "l"(src), "r"(bytes), "r"(mbar) : "memory");
}
__device__ __forceinline__ void mbar_init(uint32_t m, uint32_t cnt) {
    asm volatile("mbarrier.init.shared.b64 [%0], %1;" :: "r"(m), "r"(cnt) : "memory");
}
__device__ __forceinline__ void mbar_expect(uint32_t m, uint32_t bytes) {
    asm volatile("mbarrier.arrive.expect_tx.shared.b64 _, [%0], %1;"
                 :: "r"(m), "r"(bytes) : "memory");
}
__device__ __forceinline__ void mbar_wait(uint32_t m, uint32_t ph) {
    asm volatile(
        "{\n\t"
        ".reg .pred P1;\n\t"
        "WAIT_LOOP_%=:\n\t"
        "mbarrier.try_wait.parity.acquire.cta.shared::cta.b64 P1, [%0], %1, 0x989680;\n\t"
        "@P1 bra.uni WAIT_DONE_%=;\n\t"
        "bra.uni WAIT_LOOP_%=;\n\t"
        "WAIT_DONE_%=:\n\t"
        "}"
        :: "r"(m), "r"(ph) : "memory");
}

// SMEM layout (dynamic, 86080 B):
//   A raw fp32: 3 x 128 rows x 144B   @ 0      (stride 18432)
//   BH        : 3 x 64 rows x 80B     @ 55296  (stride 5120)
//   BL        : 3 x 64 rows x 80B     @ 70656  (stride 5120)
//   mbar[3]   : @ 86016
static constexpr int SM_A    = 0;
static constexpr int SM_BH   = 55296;
static constexpr int SM_BL   = 70656;
static constexpr int SM_MB   = 86016;
static constexpr int A_STR   = 18432;
static constexpr int B_STR   = 5120;
static constexpr int GEMM1_SMEM = 86080;

// Block tile 128(M) x 64(N), K-step 32, 16 iters. 16 warps 8x2, warp tile 16x32.
__global__ __launch_bounds__(512, 2) void k_gemm1_mma(const float* __restrict__ x) {
    extern __shared__ __align__(16) uint8_t dsm[];
    const uint32_t smBase = smem_u32(dsm);

    const int tid  = threadIdx.x;
    const int wid  = tid >> 5;
    const int lane = tid & 31;
    const int wm   = wid >> 1;
    const int wn   = wid & 1;
    const int row0 = blockIdx.x * 128;
    const int vr   = min(128, NN - row0);    // valid rows this CTA

    const int lr  = lane >> 2;
    const int lk2 = (lane & 3) * 2;

    const uint32_t bOff = (uint32_t)((wn * 32 + (((lane >> 4) & 1) * 8) + (lane & 7)) * 80
                                     + (((lane >> 3) & 1) * 8) * 2);

    if (tid == 0) {
        mbar_init(smBase + SM_MB,      1);
        mbar_init(smBase + SM_MB + 8,  1);
        mbar_init(smBase + SM_MB + 16, 1);
    }
    __syncthreads();

    float acc[4][4];
    #pragma unroll
    for (int n = 0; n < 4; n++)
        #pragma unroll
        for (int v = 0; v < 4; v++) acc[n][v] = 0.f;

    auto issueStage = [&](int ct) {
        const int buf = ct % 3;
        const uint32_t mbar = smBase + SM_MB + buf * 8;
        const uint32_t asize = (ct == 15) ? 80u : 128u;   // K tail: 20 floats = 80B
        if (tid == 0)
            mbar_expect(mbar, (uint32_t)vr * asize + 8192u);
        if (tid < 128) {
            if (tid < vr) {
                uint32_t dst = smBase + SM_A + buf * A_STR + tid * 144;
                const uint8_t* src = (const uint8_t*)x
                                   + (long long)(row0 + tid) * 2000 + ct * 128;
                bulk_cp(dst, src, asize, mbar);
            }
        } else if (tid < 256) {
            int t2 = tid - 128;       // 0..127 : 64 hi rows + 64 lo rows, 64B each
            if (t2 < 64) {
                uint32_t dst = smBase + SM_BH + buf * B_STR + t2 * 80;
                bulk_cp(dst, (const uint8_t*)(g_w1h + t2 * 256 + ct * 16), 64u, mbar);
            } else {
                int n = t2 - 64;
                uint32_t dst = smBase + SM_BL + buf * B_STR + n * 80;
                bulk_cp(dst, (const uint8_t*)(g_w1l + n * 256 + ct * 16), 64u, mbar);
            }
        }
    };

    // prologue: stages 0,1 in flight
    issueStage(0);
    issueStage(1);

    uint32_t ph0 = 0, ph1 = 0, ph2 = 0;

    #pragma unroll 1
    for (int c = 0; c < 16; c++) {
        const int buf = c % 3;
        const uint32_t mbar = smBase + SM_MB + buf * 8;
        if (buf == 0)      { mbar_wait(mbar, ph0); ph0 ^= 1; }
        else if (buf == 1) { mbar_wait(mbar, ph1); ph1 ^= 1; }
        else               { mbar_wait(mbar, ph2); ph2 ^= 1; }

        // issue stage c+2 into buf (c+2)%3 == (c-1)%3 (readers finished before
        // the __syncthreads at the end of iter c-1)
        if (c + 2 < 16) issueStage(c + 2);

        const float2* A2 = (const float2*)(dsm + SM_A + buf * A_STR);
        const uint32_t bH = smBase + SM_BH + buf * B_STR + bOff;
        const uint32_t bL = smBase + SM_BL + buf * B_STR + bOff;

        #pragma unroll
        for (int kt = 0; kt < 2; kt++) {
            const int kk  = kt * 16;
            const int cp0 = (kk + lk2) >> 1;
            const int cp1 = (kk + 8 + lk2) >> 1;

            uint32_t ah[4], al[4], bh[2][4], bl[2][4];
            {
                int r = wm * 16 + lr;
                float2 p0 = A2[r * 18 + cp0];
                float2 p1 = A2[(r + 8) * 18 + cp0];
                float2 p2 = A2[r * 18 + cp1];
                float2 p3 = A2[(r + 8) * 18 + cp1];
                cvt2(p0, ah[0], al[0]);
                cvt2(p1, ah[1], al[1]);
                cvt2(p2, ah[2], al[2]);
                cvt2(p3, ah[3], al[3]);
            }
            #pragma unroll
            for (int p = 0; p < 2; p++) {
                ldsm4(bh[p], bH + p * 1280 + kt * 32);
                ldsm4(bl[p], bL + p * 1280 + kt * 32);
            }
            #pragma unroll
            for (int n = 0; n < 4; n++) {
                const int p = n >> 1, q = (n & 1) * 2;
                uint32_t bh0 = bh[p][q], bh1 = bh[p][q + 1];
                uint32_t bl0 = bl[p][q], bl1 = bl[p][q + 1];
                mma16816(acc[n], ah[0], ah[1], ah[2], ah[3], bh0, bh1);
                mma16816(acc[n], ah[0], ah[1], ah[2], ah[3], bl0, bl1);
                mma16816(acc[n], al[0], al[1], al[2], al[3], bh0, bh1);
            }
        }
        __syncthreads();
    }

    // ---- epilogue: store raw h1 ----
    {
        int r0 = row0 + wm * 16 + lr;
        int r1 = r0 + 8;
        #pragma unroll
        for (int n = 0; n < 4; n++) {
            int cc = wn * 32 + n * 8 + lk2;
            if (r0 < NN) {
                g_h1s[r0 * HID + cc]     = acc[n][0];
                g_h1s[r0 * HID + cc + 1] = acc[n][1];
            }
            if (r1 < NN) {
                g_h1s[r1 * HID + cc]     = acc[n][2];
                g_h1s[r1 * HID + cc + 1] = acc[n][3];
            }
        }
    }
}

// ---- scan pass 2 --------------------------------------------------------------
__global__ __launch_bounds__(256) void k_scanb() {
    __shared__ int s[256];
    int t = threadIdx.x;
    int v = (t < NB) ? g_bsum[t] : 0;
    s[t] = v;
    __syncthreads();
    #pragma unroll
    for (int o = 1; o < 256; o <<= 1) {
        int u = (t >= o) ? s[t - o] : 0;
        __syncthreads();
        s[t] += u;
        __syncthreads();
    }
    g_boff[t] = s[t] - v;
    if (t == 255) g_rowptr[NN] = s[255];
}

// ---- scan pass 3: rowptr + dinv -------------------------------------------------
__global__ __launch_bounds__(256) void k_rowptr() {
    __shared__ int s[256];
    int t = threadIdx.x;
    int base = blockIdx.x * TILE + t * 2;
    int c0 = (base     < NN) ? g_cnt[base]     : 0;
    int c1 = (base + 1 < NN) ? g_cnt[base + 1] : 0;
    int part = c0 + c1;
    s[t] = part;
    __syncthreads();
    #pragma unroll
    for (int o = 1; o < 256; o <<= 1) {
        int u = (t >= o) ? s[t - o] : 0;
        __syncthreads();
        s[t] += u;
        __syncthreads();
    }
    int pre = g_boff[blockIdx.x] + s[t] - part;
    if (base < NN) {
        g_rowptr[base] = pre;
        g_dinv[base]   = rsqrtf((float)c0 + 1.0f);
    }
    if (base + 1 < NN) {
        g_rowptr[base + 1] = pre + c0;
        g_dinv[base + 1]   = rsqrtf((float)c1 + 1.0f);
    }
}

__global__ void k_scatter(const int* __restrict__ e) {
    int i = blockIdx.x * blockDim.x + threadIdx.x;
    if (i >= NE) return;
    int is64 = g_is64;
    int s = is64 ? e[2 * i]        : e[i];
    int d = is64 ? e[2 * (NE + i)] : e[NE + i];
    int p = g_rowptr[d] + atomicAdd(&g_pos[d], 1);
    g_esrc[p] = s;
}

// ------- Aggregation 1: warp/node, half-warp float4, fused relu/bias ---------
__global__ __launch_bounds__(256) void k_agg1(const float* __restrict__ b1) {
    int node = (int)((blockIdx.x * 256u + threadIdx.x) >> 5);
    int lane = threadIdx.x & 31;
    if (node >= NN) return;

    const int half = lane >> 4;
    const int fl   = lane & 15;

    const float4* H4 = (const float4*)g_h1s;
    int beg = g_rowptr[node], end = g_rowptr[node + 1];
    float dn = g_dinv[node];

    float4 acc = make_float4(0.f, 0.f, 0.f, 0.f);
    if (half == 0) {
        float4 h0 = H4[node * 16 + fl];
        acc.x = h0.x * dn; acc.y = h0.y * dn; acc.z = h0.z * dn; acc.w = h0.w * dn;
    }

    int j = beg;
    for (; j + 3 < end; j += 4) {
        int s0 = g_esrc[j + half];
        int s1 = g_esrc[j + 2 + half];
        float d0 = g_dinv[s0], d1 = g_dinv[s1];
        float4 v0 = H4[s0 * 16 + fl];
        float4 v1 = H4[s1 * 16 + fl];
        acc.x += v0.x * d0 + v1.x * d1;
        acc.y += v0.y * d0 + v1.y * d1;
        acc.z += v0.z * d0 + v1.z * d1;
        acc.w += v0.w * d0 + v1.w * d1;
    }
    for (; j + 1 < end; j += 2) {
        int s = g_esrc[j + half];
        float d = g_dinv[s];
        float4 v = H4[s * 16 + fl];
        acc.x += v.x * d; acc.y += v.y * d; acc.z += v.z * d; acc.w += v.w * d;
    }
    if (j < end && half == 0) {
        int s = g_esrc[j];
        float d = g_dinv[s];
        float4 v = H4[s * 16 + fl];
        acc.x += v.x * d; acc.y += v.y * d; acc.z += v.z * d; acc.w += v.w * d;
    }

    acc.x += __shfl_xor_sync(0xFFFFFFFFu, acc.x, 16);
    acc.y += __shfl_xor_sync(0xFFFFFFFFu, acc.y, 16);
    acc.z += __shfl_xor_sync(0xFFFFFFFFu, acc.z, 16);
    acc.w += __shfl_xor_sync(0xFFFFFFFFu, acc.w, 16);

    if (half == 0) {
        float4 bb = ((const float4*)b1)[fl];
        float4 o;
        o.x = fmaxf(dn * acc.x + bb.x, 0.f);
        o.y = fmaxf(dn * acc.y + bb.y, 0.f);
        o.z = fmaxf(dn * acc.z + bb.z, 0.f);
        o.w = fmaxf(dn * acc.w + bb.w, 0.f);
        ((float4*)g_t1)[node * 16 + fl] = o;
    }
}

// ---------------- GEMM2: gs = t1 @ W2 (raw) ----------------------------------
__global__ __launch_bounds__(256) void k_gemm2(const float* __restrict__ W2) {
    __shared__ float sw[HID * NCLS];
    __shared__ float sx[32][65];

    const int tid = threadIdx.x;
    const int row0 = blockIdx.x * 32;

    for (int i = tid; i < HID * NCLS; i += 256) sw[i] = W2[i];
    for (int i = tid; i < 32 * HID; i += 256) {
        int r = i >> 6, c = i & 63;
        int gr = row0 + r;
        sx[r][c] = (gr < NN) ? g_t1[gr * HID + c] : 0.f;
    }
    __syncthreads();

    int r  = tid >> 3;
    int cg = tid & 7;
    float acc[5] = {};
    #pragma unroll
    for (int k = 0; k < HID; k++) {
        float xv = sx[r][k];
        #pragma unroll
        for (int j = 0; j < 5; j++)
            acc[j] += xv * sw[k * NCLS + cg * 5 + j];
    }
    int gr = row0 + r;
    if (gr < NN) {
        #pragma unroll
        for (int j = 0; j < 5; j++)
            g_gs[gr * NCLS + cg * 5 + j] = acc[j];
    }
}

// --- Aggregation 2: warp/node, half-warp float4, fused bias + log_softmax ----
__global__ __launch_bounds__(256) void k_agg2(const float* __restrict__ b2,
                                              float* __restrict__ out) {
    int node = (int)((blockIdx.x * 256u + threadIdx.x) >> 5);
    int lane = threadIdx.x & 31;
    if (node >= NN) return;

    const int half = lane >> 4;
    const int fl   = lane & 15;
    const bool act = fl < 10;

    const float4* G4 = (const float4*)g_gs;
    int beg = g_rowptr[node], end = g_rowptr[node + 1];
    float dn = g_dinv[node];

    float4 acc = make_float4(0.f, 0.f, 0.f, 0.f);
    if (half == 0 && act) {
        float4 v = G4[node * 10 + fl];
        acc.x = v.x * dn; acc.y = v.y * dn; acc.z = v.z * dn; acc.w = v.w * dn;
    }

    int j = beg;
    for (; j + 3 < end; j += 4) {
        int s0 = g_esrc[j + half];
        int s1 = g_esrc[j + 2 + half];
        float d0 = g_dinv[s0], d1 = g_dinv[s1];
        if (act) {
            float4 v0 = G4[s0 * 10 + fl];
            float4 v1 = G4[s1 * 10 + fl];
            acc.x += v0.x * d0 + v1.x * d1;
            acc.y += v0.y * d0 + v1.y * d1;
            acc.z += v0.z * d0 + v1.z * d1;
            acc.w += v0.w * d0 + v1.w * d1;
        }
    }
    for (; j + 1 < end; j += 2) {
        int s = g_esrc[j + half];
        float d = g_dinv[s];
        if (act) {
            float4 v = G4[s * 10 + fl];
            acc.x += v.x * d; acc.y += v.y * d; acc.z += v.z * d; acc.w += v.w * d;
        }
    }
    if (j < end && half == 0) {
        int s = g_esrc[j];
        float d = g_dinv[s];
        if (act) {
            float4 v = G4[s * 10 + fl];
            acc.x += v.x * d; acc.y += v.y * d; acc.z += v.z * d; acc.w += v.w * d;
        }
    }

    acc.x += __shfl_xor_sync(0xFFFFFFFFu, acc.x, 16);
    acc.y += __shfl_xor_sync(0xFFFFFFFFu, acc.y, 16);
    acc.z += __shfl_xor_sync(0xFFFFFFFFu, acc.z, 16);
    acc.w += __shfl_xor_sync(0xFFFFFFFFu, acc.w, 16);

    float4 v = make_float4(-INFINITY, -INFINITY, -INFINITY, -INFINITY);
    if (act) {
        float4 bb = ((const float4*)b2)[fl];
        v.x = dn * acc.x + bb.x;
        v.y = dn * acc.y + bb.y;
        v.z = dn * acc.z + bb.z;
        v.w = dn * acc.w + bb.w;
    }

    float m = fmaxf(fmaxf(v.x, v.y), fmaxf(v.z, v.w));
    #pragma unroll
    for (int o = 16; o; o >>= 1) m = fmaxf(m, __shfl_xor_sync(0xFFFFFFFFu, m, o));

    float e = act ? (expf(v.x - m) + expf(v.y - m) + expf(v.z - m) + expf(v.w - m)) : 0.f;
    #pragma unroll
    for (int o = 16; o; o >>= 1) e += __shfl_xor_sync(0xFFFFFFFFu, e, o);
    e *= 0.5f;

    float lse = m + logf(e);
    if (half == 0 && act) {
        float4 o4;
        o4.x = v.x - lse;
        o4.y = v.y - lse;
        o4.z = v.z - lse;
        o4.w = v.w - lse;
        ((float4*)out)[node * 10 + fl] = o4;
    }
}

// ---------------- launch ------------------------------------------------------
extern "C" void kernel_launch(void* const* d_in, const int* in_sizes, int n_in,
                              void* d_out, int out_size) {
    const float* x    = (const float*)d_in[0];
    const float* W1   = (const float*)d_in[1];
    const float* b1   = (const float*)d_in[2];
    const float* W2   = (const float*)d_in[3];
    const float* b2   = (const float*)d_in[4];
    const int*   eraw = (const int*)d_in[5];
    float* out = (float*)d_out;

    (void)in_sizes; (void)n_in; (void)out_size;

    static cudaStream_t s_side = nullptr;
    static cudaEvent_t ev_fork = nullptr, ev_join = nullptr;
    static bool init_done = false;
    if (!init_done) {
        cudaStreamCreateWithFlags(&s_side, cudaStreamNonBlocking);
        cudaEventCreateWithFlags(&ev_fork, cudaEventDisableTiming);
        cudaEventCreateWithFlags(&ev_join, cudaEventDisableTiming);
        cudaFuncSetAttribute(k_gemm1_mma, cudaFuncAttributeMaxDynamicSharedMemorySize,
                             GEMM1_SMEM);
        init_done = true;
    }

    // main stream: prep, then fork
    k_prep<<<(NN + 255) / 256, 256>>>(eraw, W1);                    // launch 0
    cudaEventRecord(ev_fork, 0);
    cudaStreamWaitEvent(s_side, ev_fork, 0);

    // side stream: first part of CSR build (keeps gemm1 at capture index 3)
    k_hist   <<<(NE + 255) / 256, 256, 0, s_side>>>(eraw);          // launch 1
    k_tilesum<<<NB, 256, 0, s_side>>>();                            // launch 2

    // main stream: tensor-core GEMM1 (concurrent with CSR build)
    k_gemm1_mma<<<(NN + 127) / 128, 512, GEMM1_SMEM>>>(x);          // launch 3 <- profiled

    // side stream: rest of CSR build
    k_scanb  <<<1, 256, 0, s_side>>>();
    k_rowptr <<<NB, 256, 0, s_side>>>();
    k_scatter<<<(NE + 255) / 256, 256, 0, s_side>>>(eraw);
    cudaEventRecord(ev_join, s_side);

    // join, then the dependent tail on the main stream
    cudaStreamWaitEvent(0, ev_join, 0);
    k_agg1 <<<(NN * 32 + 255) / 256, 256>>>(b1);
    k_gemm2<<<(NN + 31) / 32, 256>>>(W2);
    k_agg2 <<<(NN * 32 + 255) / 256, 256>>>(b2, out);
}

// round 16
// speedup vs baseline: 1.0095x; 1.0095x over previous
#include <cuda_runtime.h>
#include <cuda_bf16.h>
#include <math.h>
#include <stdint.h>

// Problem constants
static constexpr int NN   = 100000;
static constexpr int NE   = 1600000;
static constexpr int FIN  = 500;
static constexpr int HID  = 64;
static constexpr int NCLS = 40;

static constexpr int TILE = 512;
static constexpr int NB   = (NN + TILE - 1) / TILE;    // 196

// ---------------- scratch ----------------------------------------------------
__device__ float g_dinv  [NN];
__device__ float g_h1s   [NN * HID];
__device__ float g_t1    [NN * HID];
__device__ float g_gs    [NN * NCLS];
__device__ int   g_esrc  [NE];
__device__ int   g_cnt   [NN];
__device__ int   g_pos   [NN];
__device__ int   g_rowptr[NN + 1];
__device__ int   g_bsum  [256];
__device__ int   g_boff  [256];
__device__ int   g_is64;
__device__ __align__(16) uint32_t g_w1h[64 * 256];
__device__ __align__(16) uint32_t g_w1l[64 * 256];

// ---------------- prep -------------------------------------------------------
__global__ void k_prep(const int* __restrict__ e, const float* __restrict__ W1) {
    int i = blockIdx.x * blockDim.x + threadIdx.x;
    if (i == 0) {
        int all0 = 1;
        #pragma unroll 1
        for (int j = 0; j < 64; j++) all0 &= (e[2 * j + 1] == 0);
        g_is64 = all0;
    }
    if (i < NN) { g_cnt[i] = 0; g_pos[i] = 0; }
    if (i < 64 * 256) {
        int n = i >> 8, kp = i & 255;
        int k0 = 2 * kp, k1 = 2 * kp + 1;
        float f0 = (k0 < FIN) ? W1[k0 * HID + n] : 0.f;
        float f1 = (k1 < FIN) ? W1[k1 * HID + n] : 0.f;
        uint32_t u0 = __float_as_uint(f0), u1 = __float_as_uint(f1);
        uint32_t hi = __byte_perm(u0, u1, 0x7632);
        float l0 = f0 - __uint_as_float(u0 & 0xFFFF0000u);
        float l1 = f1 - __uint_as_float(u1 & 0xFFFF0000u);
        uint32_t lo;
        asm("cvt.rn.bf16x2.f32 %0, %1, %2;" : "=r"(lo) : "f"(l1), "f"(l0));
        g_w1h[i] = hi;
        g_w1l[i] = lo;
    }
}

__global__ void k_hist(const int* __restrict__ e) {
    int i = blockIdx.x * blockDim.x + threadIdx.x;
    if (i >= NE) return;
    int d = g_is64 ? e[2 * (NE + i)] : e[NE + i];
    atomicAdd(&g_cnt[d], 1);
}

__global__ __launch_bounds__(256) void k_tilesum() {
    __shared__ int sred[256];
    int t = threadIdx.x;
    int base = blockIdx.x * TILE + t * 2;
    int c0 = (base     < NN) ? g_cnt[base]     : 0;
    int c1 = (base + 1 < NN) ? g_cnt[base + 1] : 0;
    sred[t] = c0 + c1;
    __syncthreads();
    #pragma unroll
    for (int o = 128; o; o >>= 1) {
        if (t < o) sred[t] += sred[t + o];
        __syncthreads();
    }
    if (t == 0) g_bsum[blockIdx.x] = sred[0];
}

// ---------------- GEMM1 (mma.sync split-bf16, cp.async 3-stage, 16 warps) ---
__device__ __forceinline__ void mma16816(float* c,
                                         uint32_t a0, uint32_t a1, uint32_t a2, uint32_t a3,
                                         uint32_t b0, uint32_t b1) {
    asm volatile(
        "mma.sync.aligned.m16n8k16.row.col.f32.bf16.bf16.f32 "
        "{%0,%1,%2,%3}, {%4,%5,%6,%7}, {%8,%9}, {%0,%1,%2,%3};"
        : "+f"(c[0]), "+f"(c[1]), "+f"(c[2]), "+f"(c[3])
        : "r"(a0), "r"(a1), "r"(a2), "r"(a3), "r"(b0), "r"(b1));
}
__device__ __forceinline__ void ldsm4(uint32_t* r, uint32_t addr) {
    asm volatile("ldmatrix.sync.aligned.m8n8.x4.shared.b16 {%0,%1,%2,%3}, [%4];"
                 : "=r"(r[0]), "=r"(r[1]), "=r"(r[2]), "=r"(r[3]) : "r"(addr));
}
__device__ __forceinline__ uint32_t smem_u32(const void* p) {
    uint32_t a;
    asm("{ .reg .u64 t; cvta.to.shared.u64 t, %1; cvt.u32.u64 %0, t; }" : "=r"(a) : "l"(p));
    return a;
}
__device__ __forceinline__ void cvt2(float2 p, uint32_t& hi, uint32_t& lo) {
    uint32_t u0 = __float_as_uint(p.x), u1 = __float_as_uint(p.y);
    hi = __byte_perm(u0, u1, 0x7632);
    float l0 = p.x - __uint_as_float(u0 & 0xFFFF0000u);
    float l1 = p.y - __uint_as_float(u1 & 0xFFFF0000u);
    asm("cvt.rn.bf16x2.f32 %0, %1, %2;" : "=r"(lo) : "f"(l1), "f"(l0));
}

// SMEM layout (dynamic, 86016 B)
static constexpr int SM_A   = 0;
static constexpr int SM_BH  = 55296;
static constexpr int SM_BL  = 70656;
static constexpr int A_STR  = 18432;
static constexpr int B_STR  = 5120;
static constexpr int GEMM1_SMEM = 86016;

// Block tile 128(M) x 64(N), K-step 32, 16 iters. 16 warps 8x2, warp tile 16x32.
__global__ __launch_bounds__(512, 2) void k_gemm1_mma(const float* __restrict__ x) {
    extern __shared__ __align__(16) uint8_t dsm[];
    const uint32_t smBase = smem_u32(dsm);

    const int tid  = threadIdx.x;
    const int wid  = tid >> 5;
    const int lane = tid & 31;
    const int wm   = wid >> 1;
    const int wn   = wid & 1;
    const int row0 = blockIdx.x * 128;

    const int lr  = lane >> 2;
    const int lk2 = (lane & 3) * 2;

    const uint32_t bOff = (uint32_t)((wn * 32 + (((lane >> 4) & 1) * 8) + (lane & 7)) * 80
                                     + (((lane >> 3) & 1) * 8) * 2);

    float acc[4][4];
    #pragma unroll
    for (int n = 0; n < 4; n++)
        #pragma unroll
        for (int v = 0; v < 4; v++) acc[n][v] = 0.f;

    auto issueStage = [&](int ct) {
        const int buf = ct % 3;
        const int k0  = ct * 32;
        const uint32_t aBase = smBase + SM_A + buf * A_STR;
        #pragma unroll
        for (int i = 0; i < 2; i++) {
            int ch  = tid + i * 512;
            int row = ch >> 3, cc = ch & 7;
            uint32_t dst = aBase + row * 144 + cc * 16;
            const float* src = x + (long long)(row0 + row) * FIN + k0 + cc * 4;
            int vb = ((row0 + row) < NN && (k0 + cc * 4 + 3) < FIN) ? 16 : 0;
            asm volatile("cp.async.cg.shared.global [%0], [%1], 16, %2;"
                         :: "r"(dst), "l"(src), "r"(vb));
        }
        {
            int t2 = tid & 255;
            int bn = t2 >> 2, bq = t2 & 3;
            if (tid < 256) {
                uint32_t dH = smBase + SM_BH + buf * B_STR + bn * 80 + bq * 16;
                const uint32_t* sH = g_w1h + bn * 256 + ct * 16 + bq * 4;
                asm volatile("cp.async.cg.shared.global [%0], [%1], 16;" :: "r"(dH), "l"(sH));
            } else {
                uint32_t dL = smBase + SM_BL + buf * B_STR + bn * 80 + bq * 16;
                const uint32_t* sL = g_w1l + bn * 256 + ct * 16 + bq * 4;
                asm volatile("cp.async.cg.shared.global [%0], [%1], 16;" :: "r"(dL), "l"(sL));
            }
        }
        asm volatile("cp.async.commit_group;");
    };

    issueStage(0);
    issueStage(1);

    #pragma unroll 1
    for (int c = 0; c < 16; c++) {
        if (c < 15) asm volatile("cp.async.wait_group 1;");
        else        asm volatile("cp.async.wait_group 0;");
        __syncthreads();
        if (c + 2 < 16) issueStage(c + 2);

        const int buf = c % 3;
        const float2* A2 = (const float2*)(dsm + SM_A + buf * A_STR);
        const uint32_t bH = smBase + SM_BH + buf * B_STR + bOff;
        const uint32_t bL = smBase + SM_BL + buf * B_STR + bOff;

        #pragma unroll
        for (int kt = 0; kt < 2; kt++) {
            const int kk  = kt * 16;
            const int cp0 = (kk + lk2) >> 1;
            const int cp1 = (kk + 8 + lk2) >> 1;

            uint32_t ah[4], al[4], bh[2][4], bl[2][4];
            {
                int r = wm * 16 + lr;
                float2 p0 = A2[r * 18 + cp0];
                float2 p1 = A2[(r + 8) * 18 + cp0];
                float2 p2 = A2[r * 18 + cp1];
                float2 p3 = A2[(r + 8) * 18 + cp1];
                cvt2(p0, ah[0], al[0]);
                cvt2(p1, ah[1], al[1]);
                cvt2(p2, ah[2], al[2]);
                cvt2(p3, ah[3], al[3]);
            }
            #pragma unroll
            for (int p = 0; p < 2; p++) {
                ldsm4(bh[p], bH + p * 1280 + kt * 32);
                ldsm4(bl[p], bL + p * 1280 + kt * 32);
            }
            #pragma unroll
            for (int n = 0; n < 4; n++) {
                const int p = n >> 1, q = (n & 1) * 2;
                uint32_t bh0 = bh[p][q], bh1 = bh[p][q + 1];
                uint32_t bl0 = bl[p][q], bl1 = bl[p][q + 1];
                mma16816(acc[n], ah[0], ah[1], ah[2], ah[3], bh0, bh1);
                mma16816(acc[n], ah[0], ah[1], ah[2], ah[3], bl0, bl1);
                mma16816(acc[n], al[0], al[1], al[2], al[3], bh0, bh1);
            }
        }
        __syncthreads();
    }

    {
        int r0 = row0 + wm * 16 + lr;
        int r1 = r0 + 8;
        #pragma unroll
        for (int n = 0; n < 4; n++) {
            int cc = wn * 32 + n * 8 + lk2;
            if (r0 < NN) {
                g_h1s[r0 * HID + cc]     = acc[n][0];
                g_h1s[r0 * HID + cc + 1] = acc[n][1];
            }
            if (r1 < NN) {
                g_h1s[r1 * HID + cc]     = acc[n][2];
                g_h1s[r1 * HID + cc + 1] = acc[n][3];
            }
        }
    }
}

// ---- scan pass 2 --------------------------------------------------------------
__global__ __launch_bounds__(256) void k_scanb() {
    __shared__ int s[256];
    int t = threadIdx.x;
    int v = (t < NB) ? g_bsum[t] : 0;
    s[t] = v;
    __syncthreads();
    #pragma unroll
    for (int o = 1; o < 256; o <<= 1) {
        int u = (t >= o) ? s[t - o] : 0;
        __syncthreads();
        s[t] += u;
        __syncthreads();
    }
    g_boff[t] = s[t] - v;
    if (t == 255) g_rowptr[NN] = s[255];
}

// ---- scan pass 3: rowptr + dinv -------------------------------------------------
__global__ __launch_bounds__(256) void k_rowptr() {
    __shared__ int s[256];
    int t = threadIdx.x;
    int base = blockIdx.x * TILE + t * 2;
    int c0 = (base     < NN) ? g_cnt[base]     : 0;
    int c1 = (base + 1 < NN) ? g_cnt[base + 1] : 0;
    int part = c0 + c1;
    s[t] = part;
    __syncthreads();
    #pragma unroll
    for (int o = 1; o < 256; o <<= 1) {
        int u = (t >= o) ? s[t - o] : 0;
        __syncthreads();
        s[t] += u;
        __syncthreads();
    }
    int pre = g_boff[blockIdx.x] + s[t] - part;
    if (base < NN) {
        g_rowptr[base] = pre;
        g_dinv[base]   = rsqrtf((float)c0 + 1.0f);
    }
    if (base + 1 < NN) {
        g_rowptr[base + 1] = pre + c0;
        g_dinv[base + 1]   = rsqrtf((float)c1 + 1.0f);
    }
}

__global__ void k_scatter(const int* __restrict__ e) {
    int i = blockIdx.x * blockDim.x + threadIdx.x;
    if (i >= NE) return;
    int is64 = g_is64;
    int s = is64 ? e[2 * i]        : e[i];
    int d = is64 ? e[2 * (NE + i)] : e[NE + i];
    int p = g_rowptr[d] + atomicAdd(&g_pos[d], 1);
    g_esrc[p] = s;
}

// ------- Aggregation 1: warp/node, half-warp float4, 8 edges in flight -------
__global__ __launch_bounds__(256) void k_agg1(const float* __restrict__ b1) {
    int node = (int)((blockIdx.x * 256u + threadIdx.x) >> 5);
    int lane = threadIdx.x & 31;
    if (node >= NN) return;

    const int half = lane >> 4;
    const int fl   = lane & 15;

    const float4* H4 = (const float4*)g_h1s;
    int beg = g_rowptr[node], end = g_rowptr[node + 1];
    float dn = g_dinv[node];

    float4 acc = make_float4(0.f, 0.f, 0.f, 0.f);
    if (half == 0) {
        float4 h0 = H4[node * 16 + fl];
        acc.x = h0.x * dn; acc.y = h0.y * dn; acc.z = h0.z * dn; acc.w = h0.w * dn;
    }

    int j = beg;
    // 8 edges per iteration: half h takes j+h, j+2+h, j+4+h, j+6+h
    for (; j + 7 < end; j += 8) {
        int s0 = g_esrc[j + half];
        int s1 = g_esrc[j + 2 + half];
        int s2 = g_esrc[j + 4 + half];
        int s3 = g_esrc[j + 6 + half];
        float d0 = g_dinv[s0], d1 = g_dinv[s1], d2 = g_dinv[s2], d3 = g_dinv[s3];
        float4 v0 = H4[s0 * 16 + fl];
        float4 v1 = H4[s1 * 16 + fl];
        float4 v2 = H4[s2 * 16 + fl];
        float4 v3 = H4[s3 * 16 + fl];
        acc.x += v0.x * d0 + v1.x * d1 + v2.x * d2 + v3.x * d3;
        acc.y += v0.y * d0 + v1.y * d1 + v2.y * d2 + v3.y * d3;
        acc.z += v0.z * d0 + v1.z * d1 + v2.z * d2 + v3.z * d3;
        acc.w += v0.w * d0 + v1.w * d1 + v2.w * d2 + v3.w * d3;
    }
    for (; j + 1 < end; j += 2) {
        int s = g_esrc[j + half];
        float d = g_dinv[s];
        float4 v = H4[s * 16 + fl];
        acc.x += v.x * d; acc.y += v.y * d; acc.z += v.z * d; acc.w += v.w * d;
    }
    if (j < end && half == 0) {
        int s = g_esrc[j];
        float d = g_dinv[s];
        float4 v = H4[s * 16 + fl];
        acc.x += v.x * d; acc.y += v.y * d; acc.z += v.z * d; acc.w += v.w * d;
    }

    acc.x += __shfl_xor_sync(0xFFFFFFFFu, acc.x, 16);
    acc.y += __shfl_xor_sync(0xFFFFFFFFu, acc.y, 16);
    acc.z += __shfl_xor_sync(0xFFFFFFFFu, acc.z, 16);
    acc.w += __shfl_xor_sync(0xFFFFFFFFu, acc.w, 16);

    if (half == 0) {
        float4 bb = ((const float4*)b1)[fl];
        float4 o;
        o.x = fmaxf(dn * acc.x + bb.x, 0.f);
        o.y = fmaxf(dn * acc.y + bb.y, 0.f);
        o.z = fmaxf(dn * acc.z + bb.z, 0.f);
        o.w = fmaxf(dn * acc.w + bb.w, 0.f);
        ((float4*)g_t1)[node * 16 + fl] = o;
    }
}

// ---------------- GEMM2: gs = t1 @ W2 (raw) ----------------------------------
__global__ __launch_bounds__(256) void k_gemm2(const float* __restrict__ W2) {
    __shared__ float sw[HID * NCLS];
    __shared__ float sx[32][65];

    const int tid = threadIdx.x;
    const int row0 = blockIdx.x * 32;

    for (int i = tid; i < HID * NCLS; i += 256) sw[i] = W2[i];
    for (int i = tid; i < 32 * HID; i += 256) {
        int r = i >> 6, c = i & 63;
        int gr = row0 + r;
        sx[r][c] = (gr < NN) ? g_t1[gr * HID + c] : 0.f;
    }
    __syncthreads();

    int r  = tid >> 3;
    int cg = tid & 7;
    float acc[5] = {};
    #pragma unroll
    for (int k = 0; k < HID; k++) {
        float xv = sx[r][k];
        #pragma unroll
        for (int j = 0; j < 5; j++)
            acc[j] += xv * sw[k * NCLS + cg * 5 + j];
    }
    int gr = row0 + r;
    if (gr < NN) {
        #pragma unroll
        for (int j = 0; j < 5; j++)
            g_gs[gr * NCLS + cg * 5 + j] = acc[j];
    }
}

// --- Aggregation 2: warp/node, half-warp float4, 8 edges in flight -----------
__global__ __launch_bounds__(256) void k_agg2(const float* __restrict__ b2,
                                              float* __restrict__ out) {
    int node = (int)((blockIdx.x * 256u + threadIdx.x) >> 5);
    int lane = threadIdx.x & 31;
    if (node >= NN) return;

    const int half = lane >> 4;
    const int fl   = lane & 15;
    const bool act = fl < 10;

    const float4* G4 = (const float4*)g_gs;
    int beg = g_rowptr[node], end = g_rowptr[node + 1];
    float dn = g_dinv[node];

    float4 acc = make_float4(0.f, 0.f, 0.f, 0.f);
    if (half == 0 && act) {
        float4 v = G4[node * 10 + fl];
        acc.x = v.x * dn; acc.y = v.y * dn; acc.z = v.z * dn; acc.w = v.w * dn;
    }

    int j = beg;
    for (; j + 7 < end; j += 8) {
        int s0 = g_esrc[j + half];
        int s1 = g_esrc[j + 2 + half];
        int s2 = g_esrc[j + 4 + half];
        int s3 = g_esrc[j + 6 + half];
        float d0 = g_dinv[s0], d1 = g_dinv[s1], d2 = g_dinv[s2], d3 = g_dinv[s3];
        if (act) {
            float4 v0 = G4[s0 * 10 + fl];
            float4 v1 = G4[s1 * 10 + fl];
            float4 v2 = G4[s2 * 10 + fl];
            float4 v3 = G4[s3 * 10 + fl];
            acc.x += v0.x * d0 + v1.x * d1 + v2.x * d2 + v3.x * d3;
            acc.y += v0.y * d0 + v1.y * d1 + v2.y * d2 + v3.y * d3;
            acc.z += v0.z * d0 + v1.z * d1 + v2.z * d2 + v3.z * d3;
            acc.w += v0.w * d0 + v1.w * d1 + v2.w * d2 + v3.w * d3;
        }
    }
    for (; j + 1 < end; j += 2) {
        int s = g_esrc[j + half];
        float d = g_dinv[s];
        if (act) {
            float4 v = G4[s * 10 + fl];
            acc.x += v.x * d; acc.y += v.y * d; acc.z += v.z * d; acc.w += v.w * d;
        }
    }
    if (j < end && half == 0) {
        int s = g_esrc[j];
        float d = g_dinv[s];
        if (act) {
            float4 v = G4[s * 10 + fl];
            acc.x += v.x * d; acc.y += v.y * d; acc.z += v.z * d; acc.w += v.w * d;
        }
    }

    acc.x += __shfl_xor_sync(0xFFFFFFFFu, acc.x, 16);
    acc.y += __shfl_xor_sync(0xFFFFFFFFu, acc.y, 16);
    acc.z += __shfl_xor_sync(0xFFFFFFFFu, acc.z, 16);
    acc.w += __shfl_xor_sync(0xFFFFFFFFu, acc.w, 16);

    float4 v = make_float4(-INFINITY, -INFINITY, -INFINITY, -INFINITY);
    if (act) {
        float4 bb = ((const float4*)b2)[fl];
        v.x = dn * acc.x + bb.x;
        v.y = dn * acc.y + bb.y;
        v.z = dn * acc.z + bb.z;
        v.w = dn * acc.w + bb.w;
    }

    float m = fmaxf(fmaxf(v.x, v.y), fmaxf(v.z, v.w));
    #pragma unroll
    for (int o = 16; o; o >>= 1) m = fmaxf(m, __shfl_xor_sync(0xFFFFFFFFu, m, o));

    float e = act ? (expf(v.x - m) + expf(v.y - m) + expf(v.z - m) + expf(v.w - m)) : 0.f;
    #pragma unroll
    for (int o = 16; o; o >>= 1) e += __shfl_xor_sync(0xFFFFFFFFu, e, o);
    e *= 0.5f;

    float lse = m + logf(e);
    if (half == 0 && act) {
        float4 o4;
        o4.x = v.x - lse;
        o4.y = v.y - lse;
        o4.z = v.z - lse;
        o4.w = v.w - lse;
        ((float4*)out)[node * 10 + fl] = o4;
    }
}

// ---------------- launch ------------------------------------------------------
extern "C" void kernel_launch(void* const* d_in, const int* in_sizes, int n_in,
                              void* d_out, int out_size) {
    const float* x    = (const float*)d_in[0];
    const float* W1   = (const float*)d_in[1];
    const float* b1   = (const float*)d_in[2];
    const float* W2   = (const float*)d_in[3];
    const float* b2   = (const float*)d_in[4];
    const int*   eraw = (const int*)d_in[5];
    float* out = (float*)d_out;

    (void)in_sizes; (void)n_in; (void)out_size;

    static cudaStream_t s_side = nullptr;
    static cudaEvent_t ev_fork = nullptr, ev_join = nullptr;
    static bool init_done = false;
    if (!init_done) {
        cudaStreamCreateWithFlags(&s_side, cudaStreamNonBlocking);
        cudaEventCreateWithFlags(&ev_fork, cudaEventDisableTiming);
        cudaEventCreateWithFlags(&ev_join, cudaEventDisableTiming);
        cudaFuncSetAttribute(k_gemm1_mma, cudaFuncAttributeMaxDynamicSharedMemorySize,
                             GEMM1_SMEM);
        init_done = true;
    }

    // main stream: prep, then fork
    k_prep<<<(NN + 255) / 256, 256>>>(eraw, W1);                    // launch 0
    cudaEventRecord(ev_fork, 0);
    cudaStreamWaitEvent(s_side, ev_fork, 0);

    // side stream: first part of CSR build (keeps gemm1 at capture index 3)
    k_hist   <<<(NE + 255) / 256, 256, 0, s_side>>>(eraw);          // launch 1
    k_tilesum<<<NB, 256, 0, s_side>>>();                            // launch 2

    // main stream: tensor-core GEMM1 (concurrent with CSR build)
    k_gemm1_mma<<<(NN + 127) / 128, 512, GEMM1_SMEM>>>(x);          // launch 3 <- profiled

    // side stream: rest of CSR build
    k_scanb  <<<1, 256, 0, s_side>>>();
    k_rowptr <<<NB, 256, 0, s_side>>>();
    k_scatter<<<(NE + 255) / 256, 256, 0, s_side>>>(eraw);
    cudaEventRecord(ev_join, s_side);

    // join, then the dependent tail on the main stream
    cudaStreamWaitEvent(0, ev_join, 0);
    k_agg1 <<<(NN * 32 + 255) / 256, 256>>>(b1);
    k_gemm2<<<(NN + 31) / 32, 256>>>(W2);
    k_agg2 <<<(NN * 32 + 255) / 256, 256>>>(b2, out);
}

// round 17
// speedup vs baseline: 1.0615x; 1.0516x over previous
#include <cuda_runtime.h>
#include <cuda_bf16.h>
#include <math.h>
#include <stdint.h>

// Problem constants
static constexpr int NN   = 100000;
static constexpr int NE   = 1600000;
static constexpr int FIN  = 500;
static constexpr int HID  = 64;
static constexpr int NCLS = 40;

static constexpr int TILE = 512;
static constexpr int NB   = (NN + TILE - 1) / TILE;    // 196

// ---------------- scratch ----------------------------------------------------
__device__ float g_dinv  [NN];
__device__ float g_h1s   [NN * HID];
__device__ float g_t1    [NN * HID];
__device__ float g_gs    [NN * NCLS];
__device__ int   g_esrc  [NE];
__device__ int   g_cnt   [NN];
__device__ int   g_pos   [NN];
__device__ int   g_rowptr[NN + 1];
__device__ int   g_bsum  [256];
__device__ int   g_boff  [256];
__device__ int   g_is64;
__device__ __align__(16) uint32_t g_w1h[64 * 256];
__device__ __align__(16) uint32_t g_w1l[64 * 256];

// ---------------- prep -------------------------------------------------------
__global__ void k_prep(const int* __restrict__ e, const float* __restrict__ W1) {
    int i = blockIdx.x * blockDim.x + threadIdx.x;
    if (i == 0) {
        int all0 = 1;
        #pragma unroll 1
        for (int j = 0; j < 64; j++) all0 &= (e[2 * j + 1] == 0);
        g_is64 = all0;
    }
    if (i < NN) { g_cnt[i] = 0; g_pos[i] = 0; }
    if (i < 64 * 256) {
        int n = i >> 8, kp = i & 255;
        int k0 = 2 * kp, k1 = 2 * kp + 1;
        float f0 = (k0 < FIN) ? W1[k0 * HID + n] : 0.f;
        float f1 = (k1 < FIN) ? W1[k1 * HID + n] : 0.f;
        uint32_t u0 = __float_as_uint(f0), u1 = __float_as_uint(f1);
        uint32_t hi = __byte_perm(u0, u1, 0x7632);
        float l0 = f0 - __uint_as_float(u0 & 0xFFFF0000u);
        float l1 = f1 - __uint_as_float(u1 & 0xFFFF0000u);
        uint32_t lo;
        asm("cvt.rn.bf16x2.f32 %0, %1, %2;" : "=r"(lo) : "f"(l1), "f"(l0));
        g_w1h[i] = hi;
        g_w1l[i] = lo;
    }
}

__global__ void k_hist(const int* __restrict__ e) {
    int i = blockIdx.x * blockDim.x + threadIdx.x;
    if (i >= NE) return;
    int d = g_is64 ? e[2 * (NE + i)] : e[NE + i];
    atomicAdd(&g_cnt[d], 1);
}

__global__ __launch_bounds__(256) void k_tilesum() {
    __shared__ int sred[256];
    int t = threadIdx.x;
    int base = blockIdx.x * TILE + t * 2;
    int c0 = (base     < NN) ? g_cnt[base]     : 0;
    int c1 = (base + 1 < NN) ? g_cnt[base + 1] : 0;
    sred[t] = c0 + c1;
    __syncthreads();
    #pragma unroll
    for (int o = 128; o; o >>= 1) {
        if (t < o) sred[t] += sred[t + o];
        __syncthreads();
    }
    if (t == 0) g_bsum[blockIdx.x] = sred[0];
}

// ---------------- GEMM1 (mma.sync split-bf16, cp.async 3-stage, 256 thr) ----
__device__ __forceinline__ void mma16816(float* c,
                                         uint32_t a0, uint32_t a1, uint32_t a2, uint32_t a3,
                                         uint32_t b0, uint32_t b1) {
    asm volatile(
        "mma.sync.aligned.m16n8k16.row.col.f32.bf16.bf16.f32 "
        "{%0,%1,%2,%3}, {%4,%5,%6,%7}, {%8,%9}, {%0,%1,%2,%3};"
        : "+f"(c[0]), "+f"(c[1]), "+f"(c[2]), "+f"(c[3])
        : "r"(a0), "r"(a1), "r"(a2), "r"(a3), "r"(b0), "r"(b1));
}
__device__ __forceinline__ void ldsm4(uint32_t* r, uint32_t addr) {
    asm volatile("ldmatrix.sync.aligned.m8n8.x4.shared.b16 {%0,%1,%2,%3}, [%4];"
                 : "=r"(r[0]), "=r"(r[1]), "=r"(r[2]), "=r"(r[3]) : "r"(addr));
}
__device__ __forceinline__ uint32_t smem_u32(const void* p) {
    uint32_t a;
    asm("{ .reg .u64 t; cvta.to.shared.u64 t, %1; cvt.u32.u64 %0, t; }" : "=r"(a) : "l"(p));
    return a;
}
__device__ __forceinline__ void cvt2(float2 p, uint32_t& hi, uint32_t& lo) {
    uint32_t u0 = __float_as_uint(p.x), u1 = __float_as_uint(p.y);
    hi = __byte_perm(u0, u1, 0x7632);
    float l0 = p.x - __uint_as_float(u0 & 0xFFFF0000u);
    float l1 = p.y - __uint_as_float(u1 & 0xFFFF0000u);
    asm("cvt.rn.bf16x2.f32 %0, %1, %2;" : "=r"(lo) : "f"(l1), "f"(l0));
}

// SMEM layout (dynamic, 86016 B)
static constexpr int SM_A   = 0;
static constexpr int SM_BH  = 55296;
static constexpr int SM_BL  = 70656;
static constexpr int A_STR  = 18432;
static constexpr int B_STR  = 5120;
static constexpr int GEMM1_SMEM = 86016;

// Block tile 128(M) x 64(N), K-step 32, 16 iters. 8 warps 4x2, warp tile 32x32.
__global__ __launch_bounds__(256) void k_gemm1_mma(const float* __restrict__ x) {
    extern __shared__ __align__(16) uint8_t dsm[];
    const uint32_t smBase = smem_u32(dsm);

    const int tid  = threadIdx.x;
    const int wid  = tid >> 5;
    const int lane = tid & 31;
    const int wm   = wid >> 1;
    const int wn   = wid & 1;
    const int row0 = blockIdx.x * 128;

    const int lr  = lane >> 2;
    const int lk2 = (lane & 3) * 2;

    const uint32_t bOff = (uint32_t)((wn * 32 + (((lane >> 4) & 1) * 8) + (lane & 7)) * 80
                                     + (((lane >> 3) & 1) * 8) * 2);

    float acc[2][4][4];
    #pragma unroll
    for (int m = 0; m < 2; m++)
        #pragma unroll
        for (int n = 0; n < 4; n++)
            #pragma unroll
            for (int v = 0; v < 4; v++) acc[m][n][v] = 0.f;

    auto issueStage = [&](int ct) {
        const int buf = ct % 3;
        const int k0  = ct * 32;
        const uint32_t aBase = smBase + SM_A + buf * A_STR;
        #pragma unroll
        for (int i = 0; i < 4; i++) {
            int ch  = tid + i * 256;
            int row = ch >> 3, cc = ch & 7;
            uint32_t dst = aBase + row * 144 + cc * 16;
            const float* src = x + (long long)(row0 + row) * FIN + k0 + cc * 4;
            int vb = ((row0 + row) < NN && (k0 + cc * 4 + 3) < FIN) ? 16 : 0;
            asm volatile("cp.async.cg.shared.global [%0], [%1], 16, %2;"
                         :: "r"(dst), "l"(src), "r"(vb));
        }
        {
            int bn = tid >> 2, bq = tid & 3;
            uint32_t dH = smBase + SM_BH + buf * B_STR + bn * 80 + bq * 16;
            uint32_t dL = smBase + SM_BL + buf * B_STR + bn * 80 + bq * 16;
            const uint32_t* sH = g_w1h + bn * 256 + ct * 16 + bq * 4;
            const uint32_t* sL = g_w1l + bn * 256 + ct * 16 + bq * 4;
            asm volatile("cp.async.cg.shared.global [%0], [%1], 16;" :: "r"(dH), "l"(sH));
            asm volatile("cp.async.cg.shared.global [%0], [%1], 16;" :: "r"(dL), "l"(sL));
        }
        asm volatile("cp.async.commit_group;");
    };

    issueStage(0);
    issueStage(1);

    #pragma unroll 1
    for (int c = 0; c < 16; c++) {
        if (c < 15) asm volatile("cp.async.wait_group 1;");
        else        asm volatile("cp.async.wait_group 0;");
        __syncthreads();
        if (c + 2 < 16) issueStage(c + 2);

        const int buf = c % 3;
        const float2* A2 = (const float2*)(dsm + SM_A + buf * A_STR);
        const uint32_t bH = smBase + SM_BH + buf * B_STR + bOff;
        const uint32_t bL = smBase + SM_BL + buf * B_STR + bOff;

        #pragma unroll
        for (int kt = 0; kt < 2; kt++) {
            const int kk  = kt * 16;
            const int cp0 = (kk + lk2) >> 1;
            const int cp1 = (kk + 8 + lk2) >> 1;

            uint32_t ah[2][4], al[2][4], bh[2][4], bl[2][4];
            #pragma unroll
            for (int m = 0; m < 2; m++) {
                int r = wm * 32 + m * 16 + lr;
                float2 p0 = A2[r * 18 + cp0];
                float2 p1 = A2[(r + 8) * 18 + cp0];
                float2 p2 = A2[r * 18 + cp1];
                float2 p3 = A2[(r + 8) * 18 + cp1];
                cvt2(p0, ah[m][0], al[m][0]);
                cvt2(p1, ah[m][1], al[m][1]);
                cvt2(p2, ah[m][2], al[m][2]);
                cvt2(p3, ah[m][3], al[m][3]);
            }
            #pragma unroll
            for (int p = 0; p < 2; p++) {
                ldsm4(bh[p], bH + p * 1280 + kt * 32);
                ldsm4(bl[p], bL + p * 1280 + kt * 32);
            }
            #pragma unroll
            for (int n = 0; n < 4; n++) {
                const int p = n >> 1, q = (n & 1) * 2;
                uint32_t bh0 = bh[p][q], bh1 = bh[p][q + 1];
                uint32_t bl0 = bl[p][q], bl1 = bl[p][q + 1];
                #pragma unroll
                for (int m = 0; m < 2; m++) {
                    mma16816(acc[m][n], ah[m][0], ah[m][1], ah[m][2], ah[m][3], bh0, bh1);
                    mma16816(acc[m][n], ah[m][0], ah[m][1], ah[m][2], ah[m][3], bl0, bl1);
                    mma16816(acc[m][n], al[m][0], al[m][1], al[m][2], al[m][3], bh0, bh1);
                }
            }
        }
        __syncthreads();
    }

    #pragma unroll
    for (int m = 0; m < 2; m++) {
        int r0 = row0 + wm * 32 + m * 16 + lr;
        int r1 = r0 + 8;
        #pragma unroll
        for (int n = 0; n < 4; n++) {
            int cc = wn * 32 + n * 8 + lk2;
            if (r0 < NN) {
                g_h1s[r0 * HID + cc]     = acc[m][n][0];
                g_h1s[r0 * HID + cc + 1] = acc[m][n][1];
            }
            if (r1 < NN) {
                g_h1s[r1 * HID + cc]     = acc[m][n][2];
                g_h1s[r1 * HID + cc + 1] = acc[m][n][3];
            }
        }
    }
}

// ---- scan pass 2 --------------------------------------------------------------
__global__ __launch_bounds__(256) void k_scanb() {
    __shared__ int s[256];
    int t = threadIdx.x;
    int v = (t < NB) ? g_bsum[t] : 0;
    s[t] = v;
    __syncthreads();
    #pragma unroll
    for (int o = 1; o < 256; o <<= 1) {
        int u = (t >= o) ? s[t - o] : 0;
        __syncthreads();
        s[t] += u;
        __syncthreads();
    }
    g_boff[t] = s[t] - v;
    if (t == 255) g_rowptr[NN] = s[255];
}

// ---- scan pass 3: rowptr + dinv -------------------------------------------------
__global__ __launch_bounds__(256) void k_rowptr() {
    __shared__ int s[256];
    int t = threadIdx.x;
    int base = blockIdx.x * TILE + t * 2;
    int c0 = (base     < NN) ? g_cnt[base]     : 0;
    int c1 = (base + 1 < NN) ? g_cnt[base + 1] : 0;
    int part = c0 + c1;
    s[t] = part;
    __syncthreads();
    #pragma unroll
    for (int o = 1; o < 256; o <<= 1) {
        int u = (t >= o) ? s[t - o] : 0;
        __syncthreads();
        s[t] += u;
        __syncthreads();
    }
    int pre = g_boff[blockIdx.x] + s[t] - part;
    if (base < NN) {
        g_rowptr[base] = pre;
        g_dinv[base]   = rsqrtf((float)c0 + 1.0f);
    }
    if (base + 1 < NN) {
        g_rowptr[base + 1] = pre + c0;
        g_dinv[base + 1]   = rsqrtf((float)c1 + 1.0f);
    }
}

__global__ void k_scatter(const int* __restrict__ e) {
    int i = blockIdx.x * blockDim.x + threadIdx.x;
    if (i >= NE) return;
    int is64 = g_is64;
    int s = is64 ? e[2 * i]        : e[i];
    int d = is64 ? e[2 * (NE + i)] : e[NE + i];
    int p = g_rowptr[d] + atomicAdd(&g_pos[d], 1);
    g_esrc[p] = s;
}

// ------- Aggregation 1: warp/node, half-warp float4 (4 edges/iter), ldcg -----
__global__ __launch_bounds__(256) void k_agg1(const float* __restrict__ b1) {
    int node = (int)((blockIdx.x * 256u + threadIdx.x) >> 5);
    int lane = threadIdx.x & 31;
    if (node >= NN) return;

    const int half = lane >> 4;
    const int fl   = lane & 15;

    const float4* H4 = (const float4*)g_h1s;
    int beg = g_rowptr[node], end = g_rowptr[node + 1];
    float dn = g_dinv[node];

    float4 acc = make_float4(0.f, 0.f, 0.f, 0.f);
    if (half == 0) {
        float4 h0 = __ldcg(&H4[node * 16 + fl]);
        acc.x = h0.x * dn; acc.y = h0.y * dn; acc.z = h0.z * dn; acc.w = h0.w * dn;
    }

    int j = beg;
    for (; j + 3 < end; j += 4) {
        int s0 = g_esrc[j + half];
        int s1 = g_esrc[j + 2 + half];
        float d0 = g_dinv[s0], d1 = g_dinv[s1];
        float4 v0 = __ldcg(&H4[s0 * 16 + fl]);
        float4 v1 = __ldcg(&H4[s1 * 16 + fl]);
        acc.x += v0.x * d0 + v1.x * d1;
        acc.y += v0.y * d0 + v1.y * d1;
        acc.z += v0.z * d0 + v1.z * d1;
        acc.w += v0.w * d0 + v1.w * d1;
    }
    for (; j + 1 < end; j += 2) {
        int s = g_esrc[j + half];
        float d = g_dinv[s];
        float4 v = __ldcg(&H4[s * 16 + fl]);
        acc.x += v.x * d; acc.y += v.y * d; acc.z += v.z * d; acc.w += v.w * d;
    }
    if (j < end && half == 0) {
        int s = g_esrc[j];
        float d = g_dinv[s];
        float4 v = __ldcg(&H4[s * 16 + fl]);
        acc.x += v.x * d; acc.y += v.y * d; acc.z += v.z * d; acc.w += v.w * d;
    }

    acc.x += __shfl_xor_sync(0xFFFFFFFFu, acc.x, 16);
    acc.y += __shfl_xor_sync(0xFFFFFFFFu, acc.y, 16);
    acc.z += __shfl_xor_sync(0xFFFFFFFFu, acc.z, 16);
    acc.w += __shfl_xor_sync(0xFFFFFFFFu, acc.w, 16);

    if (half == 0) {
        float4 bb = ((const float4*)b1)[fl];
        float4 o;
        o.x = fmaxf(dn * acc.x + bb.x, 0.f);
        o.y = fmaxf(dn * acc.y + bb.y, 0.f);
        o.z = fmaxf(dn * acc.z + bb.z, 0.f);
        o.w = fmaxf(dn * acc.w + bb.w, 0.f);
        ((float4*)g_t1)[node * 16 + fl] = o;
    }
}

// ---------------- GEMM2: gs = t1 @ W2 (raw) ----------------------------------
__global__ __launch_bounds__(256) void k_gemm2(const float* __restrict__ W2) {
    __shared__ float sw[HID * NCLS];
    __shared__ float sx[32][65];

    const int tid = threadIdx.x;
    const int row0 = blockIdx.x * 32;

    for (int i = tid; i < HID * NCLS; i += 256) sw[i] = W2[i];
    for (int i = tid; i < 32 * HID; i += 256) {
        int r = i >> 6, c = i & 63;
        int gr = row0 + r;
        sx[r][c] = (gr < NN) ? g_t1[gr * HID + c] : 0.f;
    }
    __syncthreads();

    int r  = tid >> 3;
    int cg = tid & 7;
    float acc[5] = {};
    #pragma unroll
    for (int k = 0; k < HID; k++) {
        float xv = sx[r][k];
        #pragma unroll
        for (int j = 0; j < 5; j++)
            acc[j] += xv * sw[k * NCLS + cg * 5 + j];
    }
    int gr = row0 + r;
    if (gr < NN) {
        #pragma unroll
        for (int j = 0; j < 5; j++)
            g_gs[gr * NCLS + cg * 5 + j] = acc[j];
    }
}

// --- Aggregation 2: warp/node, half-warp float4 (4 edges/iter), ldcg ---------
__global__ __launch_bounds__(256) void k_agg2(const float* __restrict__ b2,
                                              float* __restrict__ out) {
    int node = (int)((blockIdx.x * 256u + threadIdx.x) >> 5);
    int lane = threadIdx.x & 31;
    if (node >= NN) return;

    const int half = lane >> 4;
    const int fl   = lane & 15;
    const bool act = fl < 10;

    const float4* G4 = (const float4*)g_gs;
    int beg = g_rowptr[node], end = g_rowptr[node + 1];
    float dn = g_dinv[node];

    float4 acc = make_float4(0.f, 0.f, 0.f, 0.f);
    if (half == 0 && act) {
        float4 v = __ldcg(&G4[node * 10 + fl]);
        acc.x = v.x * dn; acc.y = v.y * dn; acc.z = v.z * dn; acc.w = v.w * dn;
    }

    int j = beg;
    for (; j + 3 < end; j += 4) {
        int s0 = g_esrc[j + half];
        int s1 = g_esrc[j + 2 + half];
        float d0 = g_dinv[s0], d1 = g_dinv[s1];
        if (act) {
            float4 v0 = __ldcg(&G4[s0 * 10 + fl]);
            float4 v1 = __ldcg(&G4[s1 * 10 + fl]);
            acc.x += v0.x * d0 + v1.x * d1;
            acc.y += v0.y * d0 + v1.y * d1;
            acc.z += v0.z * d0 + v1.z * d1;
            acc.w += v0.w * d0 + v1.w * d1;
        }
    }
    for (; j + 1 < end; j += 2) {
        int s = g_esrc[j + half];
        float d = g_dinv[s];
        if (act) {
            float4 v = __ldcg(&G4[s * 10 + fl]);
            acc.x += v.x * d; acc.y += v.y * d; acc.z += v.z * d; acc.w += v.w * d;
        }
    }
    if (j < end && half == 0) {
        int s = g_esrc[j];
        float d = g_dinv[s];
        if (act) {
            float4 v = __ldcg(&G4[s * 10 + fl]);
            acc.x += v.x * d; acc.y += v.y * d; acc.z += v.z * d; acc.w += v.w * d;
        }
    }

    acc.x += __shfl_xor_sync(0xFFFFFFFFu, acc.x, 16);
    acc.y += __shfl_xor_sync(0xFFFFFFFFu, acc.y, 16);
    acc.z += __shfl_xor_sync(0xFFFFFFFFu, acc.z, 16);
    acc.w += __shfl_xor_sync(0xFFFFFFFFu, acc.w, 16);

    float4 v = make_float4(-INFINITY, -INFINITY, -INFINITY, -INFINITY);
    if (act) {
        float4 bb = ((const float4*)b2)[fl];
        v.x = dn * acc.x + bb.x;
        v.y = dn * acc.y + bb.y;
        v.z = dn * acc.z + bb.z;
        v.w = dn * acc.w + bb.w;
    }

    float m = fmaxf(fmaxf(v.x, v.y), fmaxf(v.z, v.w));
    #pragma unroll
    for (int o = 16; o; o >>= 1) m = fmaxf(m, __shfl_xor_sync(0xFFFFFFFFu, m, o));

    float e = act ? (expf(v.x - m) + expf(v.y - m) + expf(v.z - m) + expf(v.w - m)) : 0.f;
    #pragma unroll
    for (int o = 16; o; o >>= 1) e += __shfl_xor_sync(0xFFFFFFFFu, e, o);
    e *= 0.5f;

    float lse = m + logf(e);
    if (half == 0 && act) {
        float4 o4;
        o4.x = v.x - lse;
        o4.y = v.y - lse;
        o4.z = v.z - lse;
        o4.w = v.w - lse;
        ((float4*)out)[node * 10 + fl] = o4;
    }
}

// ---------------- launch ------------------------------------------------------
extern "C" void kernel_launch(void* const* d_in, const int* in_sizes, int n_in,
                              void* d_out, int out_size) {
    const float* x    = (const float*)d_in[0];
    const float* W1   = (const float*)d_in[1];
    const float* b1   = (const float*)d_in[2];
    const float* W2   = (const float*)d_in[3];
    const float* b2   = (const float*)d_in[4];
    const int*   eraw = (const int*)d_in[5];
    float* out = (float*)d_out;

    (void)in_sizes; (void)n_in; (void)out_size;

    static cudaStream_t s_side = nullptr;
    static cudaEvent_t ev_fork = nullptr, ev_join = nullptr;
    static bool init_done = false;
    if (!init_done) {
        cudaStreamCreateWithFlags(&s_side, cudaStreamNonBlocking);
        cudaEventCreateWithFlags(&ev_fork, cudaEventDisableTiming);
        cudaEventCreateWithFlags(&ev_join, cudaEventDisableTiming);
        cudaFuncSetAttribute(k_gemm1_mma, cudaFuncAttributeMaxDynamicSharedMemorySize,
                             GEMM1_SMEM);
        init_done = true;
    }

    // main stream: prep, then fork
    k_prep<<<(NN + 255) / 256, 256>>>(eraw, W1);                    // launch 0
    cudaEventRecord(ev_fork, 0);
    cudaStreamWaitEvent(s_side, ev_fork, 0);

    // side stream: first part of CSR build (keeps gemm1 at capture index 3)
    k_hist   <<<(NE + 255) / 256, 256, 0, s_side>>>(eraw);          // launch 1
    k_tilesum<<<NB, 256, 0, s_side>>>();                            // launch 2

    // main stream: tensor-core GEMM1 (concurrent with CSR build)
    k_gemm1_mma<<<(NN + 127) / 128, 256, GEMM1_SMEM>>>(x);          // launch 3 <- profiled

    // side stream: rest of CSR build
    k_scanb  <<<1, 256, 0, s_side>>>();
    k_rowptr <<<NB, 256, 0, s_side>>>();
    k_scatter<<<(NE + 255) / 256, 256, 0, s_side>>>(eraw);
    cudaEventRecord(ev_join, s_side);

    // join, then the dependent tail on the main stream
    cudaStreamWaitEvent(0, ev_join, 0);
    k_agg1 <<<(NN * 32 + 255) / 256, 256>>>(b1);
    k_gemm2<<<(NN + 31) / 32, 256>>>(W2);
    k_agg2 <<<(NN * 32 + 255) / 256, 256>>>(b2, out);
}